// round 14
// baseline (speedup 1.0000x reference)
#include <cuda_runtime.h>
#include <cuda_fp16.h>
#include <cstdint>

// ----------------------------------------------------------------------------
// LightOnOCRPatchMerger, round 13: fp16 m16n8k16 GEMM, cp.async.bulk-fed,
// ldmatrix-consumed, persistent.
//   out[11955,1024] = merged[11955,4096] @ W[1024,4096]^T   (K sub-major)
// prep kernels materialize BOTH operands as half in chunk-major (BK=32),
// pre-swizzled layout: row r granule G(16B) lives at line r>>1 (128B), slot
// (G ^ ((r>>1)&3)) + 4*(r&1). Stages are contiguous 8KB per operand ->
// 2 cp.async.bulk per chunk; fragments via ldmatrix.x4 (conflict-free).
// Tile 128x128, 8 warps (warp 32x64), 2 CTAs/SM, 3-stage mbarrier ring,
// persistent grid 296 over 752 tiles (nt-fastest for A reuse in L2).
// ----------------------------------------------------------------------------

#define M_TOTAL 11955
#define M_PAD   12032
#define NCHUNK  128
#define NTILES  752            // 94 mt x 8 nt
#define STG     16384          // A 8KB + B 8KB
#define SMEM_BYTES (3 * STG)   // 49152

__device__ __half gAh[(size_t)NCHUNK * M_PAD * 32];   // 98.5 MB
__device__ __half gBh[(size_t)NCHUNK * 1024 * 32];    // 8.4 MB

// token index for merged row m, sub (geometry hardcoded from IMAGE_SIZES)
__device__ __forceinline__ int tok_of(int m, int sub) {
    const int boff[6] = {0, 2420, 4620, 6060, 9085, 10525};
    const int toff[6] = {0, 9680, 18480, 24240, 36340, 42100};
    const int gw[6]   = {88, 110, 90, 110, 64, 110};
    const int nbw[6]  = {44, 55, 45, 55, 32, 55};
    int img = 0;
    #pragma unroll
    for (int i = 1; i < 6; i++) if (m >= boff[i]) img = i;
    int local = m - boff[img];
    int bh = local / nbw[img], bw = local - bh * nbw[img];
    int w = gw[img];
    return toff[img] + 2 * bh * w + 2 * bw + (sub >> 1) * w + (sub & 1);
}

__device__ __forceinline__ unsigned pack2(float x, float y) {
    __half2 h = __floats2half2_rn(x, y);
    return *reinterpret_cast<unsigned*>(&h);
}

// swizzled byte offset within a chunk-region for (row r, granule G)
__device__ __forceinline__ int sw_off(int r, int G) {
    return (r >> 1) * 128 + (((G ^ ((r >> 1) & 3)) + 4 * (r & 1)) << 4);
}

__global__ void prep_Ah(const float* __restrict__ F) {
    int tid = threadIdx.x;
    int c = blockIdx.y;                        // chunk 0..127
    int m = blockIdx.x * 64 + (tid >> 2);
    int G = tid & 3;
    int mc = m < M_TOTAL ? m : M_TOTAL - 1;
    int sub = c >> 5;
    int d0 = (c & 31) * 32 + G * 8;
    const float* src = F + (size_t)tok_of(mc, sub) * 1024 + d0;
    float4 v0 = *reinterpret_cast<const float4*>(src);
    float4 v1 = *reinterpret_cast<const float4*>(src + 4);
    uint4 pk = make_uint4(pack2(v0.x, v0.y), pack2(v0.z, v0.w),
                          pack2(v1.x, v1.y), pack2(v1.z, v1.w));
    *reinterpret_cast<uint4*>((char*)gAh + (size_t)c * (M_PAD * 64) + sw_off(m, G)) = pk;
}

__global__ void prep_Bh(const float* __restrict__ W) {
    int tid = threadIdx.x;
    int c = blockIdx.y;
    int n = blockIdx.x * 64 + (tid >> 2);
    int G = tid & 3;
    int sub = c >> 5;
    int d0 = (c & 31) * 32 + G * 8;
    const float* src = W + (size_t)n * 4096 + sub;   // W[n][d*4+sub]
    uint4 pk = make_uint4(pack2(src[(d0 + 0) * 4], src[(d0 + 1) * 4]),
                          pack2(src[(d0 + 2) * 4], src[(d0 + 3) * 4]),
                          pack2(src[(d0 + 4) * 4], src[(d0 + 5) * 4]),
                          pack2(src[(d0 + 6) * 4], src[(d0 + 7) * 4]));
    *reinterpret_cast<uint4*>((char*)gBh + (size_t)c * 65536 + sw_off(n, G)) = pk;
}

__device__ __forceinline__ void mma16(float* d, const unsigned* a,
                                      unsigned b0, unsigned b1) {
    asm volatile(
        "mma.sync.aligned.m16n8k16.row.col.f32.f16.f16.f32 "
        "{%0,%1,%2,%3}, {%4,%5,%6,%7}, {%8,%9}, {%0,%1,%2,%3};"
        : "+f"(d[0]), "+f"(d[1]), "+f"(d[2]), "+f"(d[3])
        : "r"(a[0]), "r"(a[1]), "r"(a[2]), "r"(a[3]), "r"(b0), "r"(b1));
}

#define WAITP(a, ph) \
    asm volatile("{\n\t.reg .pred P;\n\tWL%=:\n\t" \
        "mbarrier.try_wait.parity.acquire.cta.shared::cta.b64 P, [%0], %1, 0x989680;\n\t" \
        "@P bra.uni WD%=;\n\tbra.uni WL%=;\n\tWD%=:\n\t}" :: "r"(a), "r"(ph) : "memory")

#define LDMX4(r0, r1, r2, r3, addr) \
    asm volatile("ldmatrix.sync.aligned.m8n8.x4.shared.b16 {%0,%1,%2,%3}, [%4];" \
        : "=r"(r0), "=r"(r1), "=r"(r2), "=r"(r3) : "r"(addr))

__global__ __launch_bounds__(256, 2)
void merger_gemm(float* __restrict__ out) {
    extern __shared__ char smem[];
    __shared__ uint64_t mbar[3];
    unsigned sb, mb;
    asm("{ .reg .u64 t; cvta.to.shared.u64 t, %1; cvt.u32.u64 %0, t; }"
        : "=r"(sb) : "l"((void*)smem));
    asm("{ .reg .u64 t; cvta.to.shared.u64 t, %1; cvt.u32.u64 %0, t; }"
        : "=r"(mb) : "l"((void*)mbar));

    const int tid = threadIdx.x, lane = tid & 31, warp = tid >> 5;
    const int wm = warp & 3;       // 4 warps along M (32 rows)
    const int wn = warp >> 2;      // 2 warps along N (64 cols)
    const int g = lane >> 2, tig = lane & 3;

    if (tid == 0) {
        #pragma unroll
        for (int s = 0; s < 3; s++)
            asm volatile("mbarrier.init.shared.b64 [%0], 1;"
                         :: "r"(mb + s * 8) : "memory");
    }
    __syncthreads();

    // ldmatrix lane geometry: row offset within 16-row group + granule bit
    const int roff = (lane & 7) + ((lane >> 3) & 1) * 8;   // 0..15
    const int gbit = lane >> 4;                            // 0/1

    int prod = 0, cons = 0;

    #pragma unroll 1
    for (int tile = blockIdx.x; tile < NTILES; tile += gridDim.x) {
        const int mt = tile >> 3, nt = tile & 7;
        const char* Abase = (const char*)gAh + (size_t)mt * 8192;
        const char* Bbase = (const char*)gBh + (size_t)nt * 8192;

        auto issue = [&](int chunk) {
            int s = prod % 3;
            prod++;
            unsigned bar = mb + s * 8;
            asm volatile("mbarrier.arrive.expect_tx.shared.b64 _, [%0], %1;"
                         :: "r"(bar), "r"((unsigned)STG) : "memory");
            unsigned da = sb + s * STG;
            asm volatile("cp.async.bulk.shared::cluster.global.mbarrier::complete_tx::bytes "
                         "[%0], [%1], %2, [%3];"
                         :: "r"(da), "l"(Abase + (size_t)chunk * (M_PAD * 64)),
                            "r"(8192u), "r"(bar) : "memory");
            asm volatile("cp.async.bulk.shared::cluster.global.mbarrier::complete_tx::bytes "
                         "[%0], [%1], %2, [%3];"
                         :: "r"(da + 8192), "l"(Bbase + (size_t)chunk * 65536),
                            "r"(8192u), "r"(bar) : "memory");
        };

        if (tid == 0) { issue(0); issue(1); }

        float acc[2][8][4] = {};

        #pragma unroll 1
        for (int it = 0; it < NCHUNK; it++) {
            int s = cons % 3, ph = (cons / 3) & 1;
            cons++;
            WAITP(mb + s * 8, ph);
            unsigned sA = sb + s * STG;
            unsigned sB = sA + 8192;

            #pragma unroll
            for (int kk = 0; kk < 2; kk++) {
                int G = 2 * kk + gbit;
                unsigned a[2][4];
                #pragma unroll
                for (int tt = 0; tt < 2; tt++) {
                    int rA = wm * 32 + tt * 16 + roff;
                    LDMX4(a[tt][0], a[tt][1], a[tt][2], a[tt][3],
                          sA + sw_off(rA, G));
                }
                #pragma unroll
                for (int cp = 0; cp < 4; cp++) {
                    int rB = wn * 64 + cp * 16 + roff;
                    unsigned b0a, b0b, b1a, b1b;   // {c,b0},{c+1,b0},{c,b1},{c+1,b1}
                    LDMX4(b0a, b0b, b1a, b1b, sB + sw_off(rB, G));
                    mma16(acc[0][2 * cp + 0], a[0], b0a, b1a);
                    mma16(acc[0][2 * cp + 1], a[0], b0b, b1b);
                    mma16(acc[1][2 * cp + 0], a[1], b0a, b1a);
                    mma16(acc[1][2 * cp + 1], a[1], b0b, b1b);
                }
            }
            __syncthreads();
            if (tid == 0 && it + 2 < NCHUNK) issue(it + 2);
        }

        // epilogue: acc[tt][c][0,1] -> row m0+g, cols n+0,1; [2,3] -> row +8
        #pragma unroll
        for (int tt = 0; tt < 2; tt++) {
            #pragma unroll
            for (int hh = 0; hh < 2; hh++) {
                int m = mt * 128 + wm * 32 + tt * 16 + g + hh * 8;
                if (m < M_TOTAL) {
                    #pragma unroll
                    for (int c = 0; c < 8; c++) {
                        int n = nt * 128 + wn * 64 + c * 8 + tig * 2;
                        float2 v = make_float2(acc[tt][c][hh * 2],
                                               acc[tt][c][hh * 2 + 1]);
                        *reinterpret_cast<float2*>(out + (size_t)m * 1024 + n) = v;
                    }
                }
            }
        }
    }
}

extern "C" void kernel_launch(void* const* d_in, const int* in_sizes, int n_in,
                              void* d_out, int out_size) {
    const float* feat = (const float*)d_in[0];   // [47820, 1024] fp32
    const float* W    = (const float*)d_in[1];   // [1024, 4096] fp32
    float* out = (float*)d_out;                  // [11955, 1024] fp32

    prep_Bh<<<dim3(16, 128), 256>>>(W);
    prep_Ah<<<dim3(188, 128), 256>>>(feat);

    cudaFuncSetAttribute(merger_gemm,
                         cudaFuncAttributeMaxDynamicSharedMemorySize, SMEM_BYTES);
    merger_gemm<<<296, 256, SMEM_BYTES>>>(out);
}

// round 15
// speedup vs baseline: 1.5062x; 1.5062x over previous
#include <cuda_runtime.h>
#include <cuda_fp16.h>
#include <cstdint>

// ----------------------------------------------------------------------------
// LightOnOCRPatchMerger, round 14: R11's best GEMM (pre-marshaled half
// operands, per-granule cp.async, 3-stage ring, 2 CTAs/SM) with fragment
// loads switched to ldmatrix.x4 (mapping validated in R13).
//   out[11955,1024] = merged[11955,4096] @ W[1024,4096]^T   (K sub-major)
// Tile 128x128, 8 warps (warp 32x64). Smem rows: 32 halves @ stride 40
// halves (80B) -> ldmatrix phases hit 8 distinct granules (gcd(80,128)=16).
// ----------------------------------------------------------------------------

#define M_TOTAL 11955
#define M_PAD   12032
#define NCHUNK  128            // K=4096 / BK=32
#define STG     20480          // A 128*80 + B 128*80 bytes
#define B_OFF   10240
#define SMEM_BYTES (3 * STG)   // 61440

__device__ __half g_Ah[(size_t)M_PAD * 4096];  // [m][sub*1024+d]
__device__ __half g_Wh[(size_t)1024 * 4096];   // [o][sub*1024+d]

// token index for merged row m, sub (geometry hardcoded from IMAGE_SIZES)
__device__ __forceinline__ int tok_of(int m, int sub) {
    const int boff[6] = {0, 2420, 4620, 6060, 9085, 10525};
    const int toff[6] = {0, 9680, 18480, 24240, 36340, 42100};
    const int gw[6]   = {88, 110, 90, 110, 64, 110};
    const int nbw[6]  = {44, 55, 45, 55, 32, 55};
    int img = 0;
    #pragma unroll
    for (int i = 1; i < 6; i++) if (m >= boff[i]) img = i;
    int local = m - boff[img];
    int bh = local / nbw[img], bw = local - bh * nbw[img];
    int w = gw[img];
    return toff[img] + 2 * bh * w + 2 * bw + (sub >> 1) * w + (sub & 1);
}

__global__ void prep_Ah(const float* __restrict__ F) {
    int idx = blockIdx.x * 256 + threadIdx.x;   // over M_PAD*512 (8-half units)
    int m = idx >> 9, gi = idx & 511;
    int kg = gi * 8;
    int sub = kg >> 10, d0 = kg & 1023;
    int mc = m < M_TOTAL ? m : M_TOTAL - 1;
    const float* src = F + (size_t)tok_of(mc, sub) * 1024 + d0;
    float4 v0 = *reinterpret_cast<const float4*>(src);
    float4 v1 = *reinterpret_cast<const float4*>(src + 4);
    __half2 h0 = __floats2half2_rn(v0.x, v0.y);
    __half2 h1 = __floats2half2_rn(v0.z, v0.w);
    __half2 h2 = __floats2half2_rn(v1.x, v1.y);
    __half2 h3 = __floats2half2_rn(v1.z, v1.w);
    uint4 pk = make_uint4(*reinterpret_cast<unsigned*>(&h0),
                          *reinterpret_cast<unsigned*>(&h1),
                          *reinterpret_cast<unsigned*>(&h2),
                          *reinterpret_cast<unsigned*>(&h3));
    *reinterpret_cast<uint4*>(g_Ah + (size_t)m * 4096 + kg) = pk;
}

__global__ void prep_w(const float* __restrict__ W) {
    int idx = blockIdx.x * 256 + threadIdx.x;   // over 1024*2048 half2
    int o = idx >> 11, p = idx & 2047;
    int kg = p * 2;
    int sub = kg >> 10, d = kg & 1023;
    const float* src = W + (size_t)o * 4096 + sub;
    __half2 h = __floats2half2_rn(src[d * 4], src[(d + 1) * 4]);
    reinterpret_cast<__half2*>(g_Wh)[(size_t)o * 2048 + p] = h;
}

__device__ __forceinline__ void mma16(float* d, const unsigned* a,
                                      unsigned b0, unsigned b1) {
    asm volatile(
        "mma.sync.aligned.m16n8k16.row.col.f32.f16.f16.f32 "
        "{%0,%1,%2,%3}, {%4,%5,%6,%7}, {%8,%9}, {%0,%1,%2,%3};"
        : "+f"(d[0]), "+f"(d[1]), "+f"(d[2]), "+f"(d[3])
        : "r"(a[0]), "r"(a[1]), "r"(a[2]), "r"(a[3]), "r"(b0), "r"(b1));
}

#define LDMX4(r0, r1, r2, r3, addr) \
    asm volatile("ldmatrix.sync.aligned.m8n8.x4.shared.b16 {%0,%1,%2,%3}, [%4];" \
        : "=r"(r0), "=r"(r1), "=r"(r2), "=r"(r3) : "r"(addr))

__global__ __launch_bounds__(256, 2)
void merger_gemm_f16(float* __restrict__ out) {
    extern __shared__ char smem[];
    unsigned sb;
    asm("{ .reg .u64 t; cvta.to.shared.u64 t, %1; cvt.u32.u64 %0, t; }"
        : "=r"(sb) : "l"((void*)smem));

    const int tid   = threadIdx.x;
    const int rbase = blockIdx.y * 128;
    const int nbase = blockIdx.x * 128;

    const int lane = tid & 31;
    const int warp = tid >> 5;
    const int wm = warp & 3;       // 4 warps along M (32 rows)
    const int wn = warp >> 2;      // 2 warps along N (64 cols)
    const int g   = lane >> 2;
    const int tig = lane & 3;

    // producer indices: 512 granules (16B = 8 halves) per operand, 2/thread
    const int pr = tid >> 2;           // row 0..63 (and +64)
    const int pcb = (tid & 3) * 16;    // byte offset within 64B row

    // ldmatrix lane geometry
    const int lrow = lane & 15;                    // row within 16-row group
    const unsigned lcol = (unsigned)(lane >> 4) * 16;  // 0 or 16 bytes (8 halves)

    float acc[2][8][4] = {};

    auto issue = [&](int t, int s) {
        int sub = t >> 5;
        int d0  = (t & 31) * 32;
        unsigned stg = sb + s * STG;
        const __half* srcA = g_Ah + (size_t)(rbase + pr) * 4096 + sub * 1024 + d0;
        const __half* srcB = g_Wh + (size_t)(nbase + pr) * 4096 + sub * 1024 + d0;
        #pragma unroll
        for (int i = 0; i < 2; i++) {
            unsigned dA = stg + (pr + i * 64) * 80 + pcb;
            unsigned dB = stg + B_OFF + (pr + i * 64) * 80 + pcb;
            asm volatile("cp.async.cg.shared.global [%0], [%1], 16;"
                         :: "r"(dA), "l"((const char*)(srcA + (size_t)i * 64 * 4096) + pcb));
            asm volatile("cp.async.cg.shared.global [%0], [%1], 16;"
                         :: "r"(dB), "l"((const char*)(srcB + (size_t)i * 64 * 4096) + pcb));
        }
        asm volatile("cp.async.commit_group;");
    };

    issue(0, 0);
    issue(1, 1);

    int s = 0;
    #pragma unroll 1
    for (int t = 0; t < NCHUNK; t++) {
        asm volatile("cp.async.wait_group 1;");
        __syncthreads();
        if (t + 2 < NCHUNK) issue(t + 2, (s + 2) % 3);
        else asm volatile("cp.async.commit_group;");   // keep group count in step

        unsigned sA = sb + s * STG;
        unsigned sB = sA + B_OFF;
        #pragma unroll
        for (int kk = 0; kk < 2; kk++) {
            unsigned cofs = kk * 32 + lcol;            // byte col offset
            unsigned a[2][4];
            #pragma unroll
            for (int tt = 0; tt < 2; tt++) {
                unsigned ad = sA + (unsigned)(wm * 32 + tt * 16 + lrow) * 80 + cofs;
                LDMX4(a[tt][0], a[tt][1], a[tt][2], a[tt][3], ad);
            }
            #pragma unroll
            for (int cp = 0; cp < 4; cp++) {
                unsigned bd = sB + (unsigned)(wn * 64 + cp * 16 + lrow) * 80 + cofs;
                unsigned b0a, b0b, b1a, b1b;
                LDMX4(b0a, b0b, b1a, b1b, bd);
                mma16(acc[0][2 * cp + 0], a[0], b0a, b1a);
                mma16(acc[0][2 * cp + 1], a[0], b0b, b1b);
                mma16(acc[1][2 * cp + 0], a[1], b0a, b1a);
                mma16(acc[1][2 * cp + 1], a[1], b0b, b1b);
            }
        }
        if (++s == 3) s = 0;
    }

    // epilogue: acc[tt][c][0,1] -> row m0+g cols n,n+1; [2,3] -> row m0+g+8
    #pragma unroll
    for (int tt = 0; tt < 2; tt++) {
        #pragma unroll
        for (int hh = 0; hh < 2; hh++) {
            int m = rbase + wm * 32 + tt * 16 + g + hh * 8;
            if (m < M_TOTAL) {
                #pragma unroll
                for (int c = 0; c < 8; c++) {
                    int n = nbase + wn * 64 + c * 8 + tig * 2;
                    float2 v = make_float2(acc[tt][c][hh * 2], acc[tt][c][hh * 2 + 1]);
                    *reinterpret_cast<float2*>(out + (size_t)m * 1024 + n) = v;
                }
            }
        }
    }
}

extern "C" void kernel_launch(void* const* d_in, const int* in_sizes, int n_in,
                              void* d_out, int out_size) {
    const float* feat = (const float*)d_in[0];   // [47820, 1024] fp32
    const float* W    = (const float*)d_in[1];   // [1024, 4096] fp32
    float* out = (float*)d_out;                  // [11955, 1024] fp32

    prep_w<<<(1024 * 2048) / 256, 256>>>(W);
    prep_Ah<<<(M_PAD * 512) / 256, 256>>>(feat);

    cudaFuncSetAttribute(merger_gemm_f16,
                         cudaFuncAttributeMaxDynamicSharedMemorySize, SMEM_BYTES);
    dim3 grid(8, 94);   // 8 N-tiles x 94 M-tiles of 128x128
    merger_gemm_f16<<<grid, 256, SMEM_BYTES>>>(out);
}

// round 16
// speedup vs baseline: 1.8789x; 1.2475x over previous
#include <cuda_runtime.h>
#include <cuda_fp16.h>
#include <cstdint>

// ----------------------------------------------------------------------------
// LightOnOCRPatchMerger, round 15: fp16 m16n8k16 GEMM, full cp.async.bulk feed.
//   out[11955,1024] = merged[11955,4096] @ W[1024,4096]^T   (K sub-major)
// Both operands pre-marshaled to half, chunk-major (BK=32), row stride 64B,
// granule-swizzled: granule G (16B, k=G*8..G*8+7) of row r lives at slot
// G ^ ((r>>1)&3). Each stage (A 8KB + B 8KB) = 2 cp.async.bulk ops into a
// 3-stage mbarrier ring (R7-proven mechanism, R11-proven rhythm). Fragments
// via ldmatrix.x4 (R14-validated mapping; per-phase banksets distinct).
// Tile 128x128, 8 warps (warp 32x64), 2 CTAs/SM, grid (8, 94).
// ----------------------------------------------------------------------------

#define M_TOTAL 11955
#define M_PAD   12032
#define NCHUNK  128            // K=4096 / BK=32
#define STG     16384          // A 8KB + B 8KB
#define SMEM_BYTES (3 * STG)   // 49152

__device__ __half gAh[(size_t)NCHUNK * M_PAD * 32];   // 98.5 MB, [c][m][32]
__device__ __half gBh[(size_t)NCHUNK * 1024 * 32];    // 8.4 MB,  [c][n][32]

// token index for merged row m, sub (geometry hardcoded from IMAGE_SIZES)
__device__ __forceinline__ int tok_of(int m, int sub) {
    const int boff[6] = {0, 2420, 4620, 6060, 9085, 10525};
    const int toff[6] = {0, 9680, 18480, 24240, 36340, 42100};
    const int gw[6]   = {88, 110, 90, 110, 64, 110};
    const int nbw[6]  = {44, 55, 45, 55, 32, 55};
    int img = 0;
    #pragma unroll
    for (int i = 1; i < 6; i++) if (m >= boff[i]) img = i;
    int local = m - boff[img];
    int bh = local / nbw[img], bw = local - bh * nbw[img];
    int w = gw[img];
    return toff[img] + 2 * bh * w + 2 * bw + (sub >> 1) * w + (sub & 1);
}

__device__ __forceinline__ unsigned pack2(float x, float y) {
    __half2 h = __floats2half2_rn(x, y);
    return *reinterpret_cast<unsigned*>(&h);
}

__global__ void prep_Ah(const float* __restrict__ F) {
    int tid = threadIdx.x;
    int c = blockIdx.y;                        // chunk 0..127
    int m = blockIdx.x * 64 + (tid >> 2);      // row 0..M_PAD-1
    int G = tid & 3;
    int mc = m < M_TOTAL ? m : M_TOTAL - 1;
    int sub = c >> 5;
    int d0 = (c & 31) * 32 + G * 8;
    const float* src = F + (size_t)tok_of(mc, sub) * 1024 + d0;
    float4 v0 = *reinterpret_cast<const float4*>(src);
    float4 v1 = *reinterpret_cast<const float4*>(src + 4);
    uint4 pk = make_uint4(pack2(v0.x, v0.y), pack2(v0.z, v0.w),
                          pack2(v1.x, v1.y), pack2(v1.z, v1.w));
    int slot = G ^ ((m >> 1) & 3);
    *reinterpret_cast<uint4*>((char*)gAh + (size_t)c * (M_PAD * 64)
                              + m * 64 + slot * 16) = pk;
}

__global__ void prep_Bm(const float* __restrict__ W) {
    int idx = blockIdx.x * 256 + threadIdx.x;  // over 128*1024*16 half2-units
    int c = idx >> 14;
    int rem = idx & 16383;
    int n = rem >> 4;
    int jp = rem & 15;                         // half-pair index, j = 2*jp
    int sub = c >> 5;
    int d0 = (c & 31) * 32 + 2 * jp;           // d index; W col = d*4 + sub
    const float* src = W + (size_t)n * 4096 + sub;
    unsigned h = pack2(src[d0 * 4], src[(d0 + 1) * 4]);
    int G = jp >> 2;
    int slot = G ^ ((n >> 1) & 3);
    *reinterpret_cast<unsigned*>((char*)gBh + (size_t)c * 65536
                                 + n * 64 + slot * 16 + ((2 * jp) & 7) * 2) = h;
}

__device__ __forceinline__ void mma16(float* d, const unsigned* a,
                                      unsigned b0, unsigned b1) {
    asm volatile(
        "mma.sync.aligned.m16n8k16.row.col.f32.f16.f16.f32 "
        "{%0,%1,%2,%3}, {%4,%5,%6,%7}, {%8,%9}, {%0,%1,%2,%3};"
        : "+f"(d[0]), "+f"(d[1]), "+f"(d[2]), "+f"(d[3])
        : "r"(a[0]), "r"(a[1]), "r"(a[2]), "r"(a[3]), "r"(b0), "r"(b1));
}

#define WAITP(a, ph) \
    asm volatile("{\n\t.reg .pred P;\n\tWL%=:\n\t" \
        "mbarrier.try_wait.parity.acquire.cta.shared::cta.b64 P, [%0], %1, 0x989680;\n\t" \
        "@P bra.uni WD%=;\n\tbra.uni WL%=;\n\tWD%=:\n\t}" :: "r"(a), "r"(ph) : "memory")

#define LDMX4(r0, r1, r2, r3, addr) \
    asm volatile("ldmatrix.sync.aligned.m8n8.x4.shared.b16 {%0,%1,%2,%3}, [%4];" \
        : "=r"(r0), "=r"(r1), "=r"(r2), "=r"(r3) : "r"(addr))

__global__ __launch_bounds__(256, 2)
void merger_gemm_f16(float* __restrict__ out) {
    extern __shared__ char smem[];
    __shared__ uint64_t mbar[3];
    unsigned sb, mb;
    asm("{ .reg .u64 t; cvta.to.shared.u64 t, %1; cvt.u32.u64 %0, t; }"
        : "=r"(sb) : "l"((void*)smem));
    asm("{ .reg .u64 t; cvta.to.shared.u64 t, %1; cvt.u32.u64 %0, t; }"
        : "=r"(mb) : "l"((void*)mbar));

    const int tid   = threadIdx.x;
    const int rbase = blockIdx.y * 128;
    const int nbase = blockIdx.x * 128;

    const int lane = tid & 31;
    const int warp = tid >> 5;
    const int wm = warp & 3;       // 4 warps along M (32 rows)
    const int wn = warp >> 2;      // 2 warps along N (64 cols)
    const int g   = lane >> 2;
    const int tig = lane & 3;

    // ldmatrix lane geometry
    const int lrow = lane & 15;
    const int gsel = lane >> 4;    // 0/1: low/high granule of the k16 step

    if (tid == 0) {
        #pragma unroll
        for (int s = 0; s < 3; s++)
            asm volatile("mbarrier.init.shared.b64 [%0], 1;"
                         :: "r"(mb + s * 8) : "memory");
    }
    __syncthreads();

    const char* Abase = (const char*)gAh + (size_t)rbase * 64;
    const char* Bbase = (const char*)gBh + (size_t)nbase * 64;

    auto issue = [&](int t) {
        int s = t % 3;
        unsigned bar = mb + s * 8;
        asm volatile("mbarrier.arrive.expect_tx.shared.b64 _, [%0], %1;"
                     :: "r"(bar), "r"((unsigned)STG) : "memory");
        unsigned da = sb + s * STG;
        asm volatile("cp.async.bulk.shared::cluster.global.mbarrier::complete_tx::bytes "
                     "[%0], [%1], %2, [%3];"
                     :: "r"(da), "l"(Abase + (size_t)t * (M_PAD * 64)),
                        "r"(8192u), "r"(bar) : "memory");
        asm volatile("cp.async.bulk.shared::cluster.global.mbarrier::complete_tx::bytes "
                     "[%0], [%1], %2, [%3];"
                     :: "r"(da + 8192), "l"(Bbase + (size_t)t * 65536),
                        "r"(8192u), "r"(bar) : "memory");
    };

    if (tid == 0) { issue(0); issue(1); }

    // per-thread fragment address components
    int arow0 = wm * 32 + lrow, arow1 = arow0 + 16;
    unsigned aoff0 = arow0 * 64, aoff1 = arow1 * 64;
    int aswz0 = (arow0 >> 1) & 3, aswz1 = (arow1 >> 1) & 3;

    float acc[2][8][4] = {};

    #pragma unroll 1
    for (int t = 0; t < NCHUNK; t++) {
        int s = t % 3, ph = (t / 3) & 1;
        WAITP(mb + s * 8, ph);
        __syncthreads();                 // all warps done with slot of t-1
        if (tid == 0 && t + 2 < NCHUNK) issue(t + 2);

        unsigned sA = sb + s * STG;
        unsigned sB = sA + 8192;
        #pragma unroll
        for (int kk = 0; kk < 2; kk++) {
            int G = 2 * kk + gsel;
            unsigned a[2][4];
            LDMX4(a[0][0], a[0][1], a[0][2], a[0][3],
                  sA + aoff0 + ((unsigned)(G ^ aswz0) << 4));
            LDMX4(a[1][0], a[1][1], a[1][2], a[1][3],
                  sA + aoff1 + ((unsigned)(G ^ aswz1) << 4));
            #pragma unroll
            for (int cp = 0; cp < 4; cp++) {
                int brow = wn * 64 + cp * 16 + lrow;
                unsigned bd = sB + (unsigned)brow * 64
                            + ((unsigned)(G ^ ((brow >> 1) & 3)) << 4);
                unsigned b0a, b0b, b1a, b1b;
                LDMX4(b0a, b0b, b1a, b1b, bd);
                mma16(acc[0][2 * cp + 0], a[0], b0a, b1a);
                mma16(acc[0][2 * cp + 1], a[0], b0b, b1b);
                mma16(acc[1][2 * cp + 0], a[1], b0a, b1a);
                mma16(acc[1][2 * cp + 1], a[1], b0b, b1b);
            }
        }
    }

    // epilogue: acc[tt][c][0,1] -> row m0+g cols n,n+1; [2,3] -> row m0+g+8
    #pragma unroll
    for (int tt = 0; tt < 2; tt++) {
        #pragma unroll
        for (int hh = 0; hh < 2; hh++) {
            int m = rbase + wm * 32 + tt * 16 + g + hh * 8;
            if (m < M_TOTAL) {
                #pragma unroll
                for (int c = 0; c < 8; c++) {
                    int n = nbase + wn * 64 + c * 8 + tig * 2;
                    float2 v = make_float2(acc[tt][c][hh * 2], acc[tt][c][hh * 2 + 1]);
                    *reinterpret_cast<float2*>(out + (size_t)m * 1024 + n) = v;
                }
            }
        }
    }
}

extern "C" void kernel_launch(void* const* d_in, const int* in_sizes, int n_in,
                              void* d_out, int out_size) {
    const float* feat = (const float*)d_in[0];   // [47820, 1024] fp32
    const float* W    = (const float*)d_in[1];   // [1024, 4096] fp32
    float* out = (float*)d_out;                  // [11955, 1024] fp32

    prep_Bm<<<(128 * 1024 * 16) / 256, 256>>>(W);
    prep_Ah<<<dim3(188, 128), 256>>>(feat);

    cudaFuncSetAttribute(merger_gemm_f16,
                         cudaFuncAttributeMaxDynamicSharedMemorySize, SMEM_BYTES);
    dim3 grid(8, 94);   // 8 N-tiles x 94 M-tiles of 128x128
    merger_gemm_f16<<<grid, 256, SMEM_BYTES>>>(out);
}